// round 15
// baseline (speedup 1.0000x reference)
#include <cuda_runtime.h>
#include <cuda_fp16.h>
#include <cstdint>

#define K_H  128
#define K_W  128
#define K_HW 16384
#define K_B  4
#define K_NS 33

// ======================= device scratch (static, no alloc) =======================
__device__ __align__(16) __half g_a1[(size_t)(K_B*K_HW + 2*K_W)*576];
__device__ __align__(16) __half g_a2[(size_t)(K_B*K_HW + 2*K_W)*256];
__device__ __align__(16) __half g_a3[(size_t)(K_B*K_HW + 2*K_W)*128];
__device__ __align__(16) __half g_y1[(size_t)K_B*K_HW*256];   // pre-GN conv outs, fp16
__device__ __align__(16) __half g_y2[(size_t)K_B*K_HW*128];
__device__ __align__(16) __half g_y3[(size_t)K_B*K_HW*64];
__device__ __align__(16) __half g_w1[9*256*576];
__device__ __align__(16) __half g_w2[9*128*256];
__device__ __align__(16) __half g_w3[9*64*128];
__device__ float g_gs[3][64], g_gq[3][64];
__device__ float g_psum[K_B*K_NS*64];
__device__ float g_pcnt[K_B*K_NS];

// ======================= helpers =======================
__device__ __forceinline__ uint32_t smem_u32(const void* p) {
    uint32_t a;
    asm("{ .reg .u64 t; cvta.to.shared.u64 t, %1; cvt.u32.u64 %0, t; }" : "=r"(a) : "l"(p));
    return a;
}
__device__ __forceinline__ void cp16(uint32_t dst, const void* src, uint32_t sz){
    asm volatile("cp.async.cg.shared.global [%0], [%1], 16, %2;" :: "r"(dst), "l"(src), "r"(sz));
}
#define CP_COMMIT() asm volatile("cp.async.commit_group;" ::: "memory")
#define CP_WAIT0()  asm volatile("cp.async.wait_group 0;"  ::: "memory")
__device__ __forceinline__ void ldsm4(uint32_t (&r)[4], uint32_t a){
    asm volatile("ldmatrix.sync.aligned.m8n8.x4.shared.b16 {%0,%1,%2,%3}, [%4];"
        : "=r"(r[0]), "=r"(r[1]), "=r"(r[2]), "=r"(r[3]) : "r"(a));
}
__device__ __forceinline__ void mma16816(float (&d)[4], const uint32_t (&a)[4],
                                         uint32_t b0, uint32_t b1){
    asm volatile(
        "mma.sync.aligned.m16n8k16.row.col.f32.f16.f16.f32 "
        "{%0,%1,%2,%3},{%4,%5,%6,%7},{%8,%9},{%0,%1,%2,%3};"
        : "+f"(d[0]), "+f"(d[1]), "+f"(d[2]), "+f"(d[3])
        : "r"(a[0]), "r"(a[1]), "r"(a[2]), "r"(a[3]), "r"(b0), "r"(b1));
}

// ======================= setup: repack weights + zero accumulators (one launch) =======================
template<int LAYER>
__device__ __forceinline__ void repack_body(const float* __restrict__ w, int bid, int nb){
    constexpr int Cin  = (LAYER==1)?576:(LAYER==2)?256:128;
    constexpr int Cout = (LAYER==1)?256:(LAYER==2)?128:64;
    __half* wp = (LAYER==1)?g_w1:(LAYER==2)?g_w2:g_w3;
    int n = Cout*Cin*9;
    for (int i = bid*256 + threadIdx.x; i < n; i += nb*256){
        int k  = i % 9;
        int t  = i / 9;
        int ci = t % Cin;
        int co = t / Cin;
        wp[((size_t)k*Cout + co)*Cin + ci] = __float2half_rn(w[i]);
    }
}

__global__ void repack_all(const float* __restrict__ w1, const float* __restrict__ w2,
                           const float* __restrict__ w3){
    int bid = blockIdx.x;
    if (bid < 512)      repack_body<1>(w1, bid, 512);
    else if (bid < 768) repack_body<2>(w2, bid - 512, 256);
    else if (bid < 896) repack_body<3>(w3, bid - 768, 128);
    else {
        int i = (bid - 896)*256 + threadIdx.x;
        if (i < K_B*K_NS*64) g_psum[i] = 0.f;
        if (i < K_B*K_NS)    g_pcnt[i] = 0.f;
        if (i < 64){
            g_gs[0][i]=0.f; g_gs[1][i]=0.f; g_gs[2][i]=0.f;
            g_gq[0][i]=0.f; g_gq[1][i]=0.f; g_gq[2][i]=0.f;
        }
    }
}

__global__ void xform1(const float* __restrict__ x, const float* __restrict__ wc,
                       const float* __restrict__ bc){
    __shared__ float tile[64][129];
    int cblk = blockIdx.x, h = blockIdx.y, b = blockIdx.z, tid = threadIdx.x;
    if (cblk < 8){
        for (int i = tid; i < 64*128; i += 256){
            int ci = i >> 7, w = i & 127;
            tile[ci][w] = x[(((size_t)b*512 + cblk*64 + ci)*K_H + h)*K_W + w];
        }
    } else {
        for (int i = tid; i < 64*128; i += 256){
            int ci = i >> 7, w = i & 127;
            tile[ci][w] = fmaxf(wc[2*ci]*(float)w + wc[2*ci+1]*(float)h + bc[ci], 0.f);
        }
    }
    __syncthreads();
    for (int i = tid; i < 64*128; i += 256){
        int px = i >> 6, c = i & 63;
        size_t o = (size_t)(K_W)*576 + (((size_t)b*K_H + h)*K_W + px)*576 + cblk*64 + c;
        g_a1[o] = __float2half_rn(tile[c][px]);
    }
}

// GN finalize (inline) + relu + fp16 pack ; 8 elems/thread, fp16 in & out
template<int L>
__global__ void act_xform(const float* __restrict__ gamma, const float* __restrict__ beta){
    constexpr int C    = (L==2)?256:128;
    constexpr int Cg   = 32;
    constexpr int SIDX = L-2;
    const __half* __restrict__ y = (L==2)?g_y1:g_y2;
    __half* __restrict__ ah = ((L==2)?g_a2:g_a3) + (size_t)K_W*C;
    size_t i8 = ((size_t)blockIdx.x*256 + threadIdx.x)*8;
    if (i8 >= (size_t)K_B*K_HW*C) return;
    int c = (int)(i8 % C);
    int b = (int)(i8 / ((size_t)K_HW*C));
    int g = b*(C/Cg) + c/Cg;                 // c%8==0, Cg=32 -> all 8 lanes same group
    const float n   = (float)Cg * (float)K_HW;
    float mu  = g_gs[SIDX][g] / n;
    float var = g_gq[SIDX][g] / n - mu*mu;
    float inv = rsqrtf(var + 1e-5f);
    float4 gmA = *(const float4*)(gamma + c);
    float4 gmB = *(const float4*)(gamma + c + 4);
    float4 btA = *(const float4*)(beta  + c);
    float4 btB = *(const float4*)(beta  + c + 4);
    float s[8] = {gmA.x*inv, gmA.y*inv, gmA.z*inv, gmA.w*inv,
                  gmB.x*inv, gmB.y*inv, gmB.z*inv, gmB.w*inv};
    float t[8] = {btA.x - mu*s[0], btA.y - mu*s[1], btA.z - mu*s[2], btA.w - mu*s[3],
                  btB.x - mu*s[4], btB.y - mu*s[5], btB.z - mu*s[6], btB.w - mu*s[7]};
    uint4 raw = *(const uint4*)(y + i8);
    const __half2* hp = (const __half2*)&raw;
    __half2 o4[4];
    #pragma unroll
    for (int j = 0; j < 4; j++){
        float2 v = __half22float2(hp[j]);
        float r0 = fmaxf(fmaf(s[2*j],   v.x, t[2*j]),   0.f);
        float r1 = fmaxf(fmaf(s[2*j+1], v.y, t[2*j+1]), 0.f);
        o4[j] = __floats2half2_rn(r0, r1);
    }
    *(uint4*)(ah + i8) = *(uint4*)o4;
}

// ======================= conv3x3: plain fp16 mma.sync, BN=128, occ2, 1 barrier/group =======================
template<int LAYER>
__global__ void __launch_bounds__(256,2)
conv_hmma(const float* __restrict__ bias){
    constexpr int Cin  = (LAYER==1)?576:(LAYER==2)?256:128;
    constexpr int Cout = (LAYER==1)?256:(LAYER==2)?128:64;
    constexpr int Cg   = (LAYER==3)?16:32;
    constexpr int BN   = (Cout>=128)?128:64;
    constexpr int NCB  = Cin/32;
    constexpr int NG   = 3*NCB;
    constexpr int NI   = BN/16;
    constexpr int BIT  = BN/64;
    constexpr int APL  = 10496;
    constexpr int BPL  = BN*80;
    constexpr int ABYT = 2*APL;
    constexpr int WK   = Cout*Cin;
    constexpr int A_KYADJ = K_W*Cin - (NCB-1)*32;
    constexpr int W_KYADJ = 3*Cout*Cin - (NCB-1)*32;

    const __half* __restrict__ act = ((LAYER==1)?g_a1:(LAYER==2)?g_a2:g_a3) + (size_t)K_W*Cin;
    const __half* __restrict__ w_p = (LAYER==1)?g_w1:(LAYER==2)?g_w2:g_w3;
    __half* __restrict__ out = (LAYER==1)?g_y1:(LAYER==2)?g_y2:g_y3;

    extern __shared__ __align__(128) char dsm[];
    const uint32_t sbase = smem_u32(dsm);

    const int tid  = threadIdx.x;
    const int lane = tid & 31;
    const int wm   = (tid >> 5) & 3;
    const int wn   = tid >> 7;
    const int h    = blockIdx.x;
    const int b    = blockIdx.y;
    const int cob  = blockIdx.z*BN;

    if (tid < 80){
        int pl = tid/40, rem = tid%40;
        uint32_t row = (rem >= 20) ? 129u : 0u;
        *(uint32_t*)(dsm + pl*APL + row*80 + (rem%20)*4) = 0u;
    }

    float acc[2][NI][4];
    #pragma unroll
    for (int mi=0;mi<2;mi++)
        #pragma unroll
        for (int ni=0;ni<NI;ni++)
            #pragma unroll
            for (int j=0;j<4;j++) acc[mi][ni][j] = 0.f;

    uint32_t dA[2], dB[BIT];
    int atoff[2], wtoff[BIT];
    #pragma unroll
    for (int it = 0; it < 2; it++){
        int idx = it*256 + tid, r = idx >> 2, q = idx & 3;
        dA[it]    = sbase + (r+1)*80 + q*16;
        atoff[it] = r*Cin + q*8;
    }
    #pragma unroll
    for (int it = 0; it < BIT; it++){
        int idx = it*256 + tid, r = idx >> 2, q = idx & 3;
        dB[it]    = sbase + ABYT + r*80 + q*16;
        wtoff[it] = r*Cin + q*8;
    }

    const __half* pA = act + ((size_t)(b*K_H + h) - 1)*K_W*Cin;
    const __half* pW = w_p + (size_t)cob*Cin;
    int cbL = 0, kyL = 0;
    const uint32_t vmask = ((h > 0) ? 1u : 0u) | 2u | ((h < K_H-1) ? 4u : 0u);
    uint32_t szA = (vmask & 1u) ? 16u : 0u;

#define ISSUE_LOAD(POFF_A, POFF_B) { \
        _Pragma("unroll") \
        for (int it = 0; it < 2; it++) \
            cp16(dA[it] + (POFF_A), pA + atoff[it], szA); \
        _Pragma("unroll") \
        for (int kx = 0; kx < 3; kx++){ \
            _Pragma("unroll") \
            for (int it = 0; it < BIT; it++) \
                cp16(dB[it] + (POFF_B) + kx*BPL, pW + kx*WK + wtoff[it], 16u); \
        } \
        if (++cbL < NCB){ pA += 32; pW += 32; } \
        else { cbL = 0; ++kyL; pA += A_KYADJ; pW += W_KYADJ; \
               szA = ((vmask >> kyL) & 1u) ? 16u : 0u; } }

    const uint32_t aoff0 = (uint32_t)((wm*32 + (lane & 15))*80 + (lane >> 4)*16);
    const uint32_t boff  = (uint32_t)((wn*(BN/2) + (lane & 15))*80 + (lane >> 4)*16);

    uint32_t poffA = 0, poffB = 0;
    ISSUE_LOAD(0, 0); CP_COMMIT();

    #pragma unroll 1
    for (int g = 0; g < NG; ++g){
        CP_WAIT0();
        __syncthreads();

        if (g + 1 < NG) ISSUE_LOAD(APL - poffA, 3*BPL - poffB);
        CP_COMMIT();

        const uint32_t Ab  = sbase + poffA;
        const uint32_t Bb0 = sbase + ABYT + poffB;
        poffA ^= APL; poffB ^= 3*BPL;

        #pragma unroll
        for (int kx = 0; kx < 3; kx++){
            const uint32_t Bb = Bb0 + kx*BPL;
            const uint32_t ao = aoff0 + kx*80;
            uint32_t ah[2][2][4];
            #pragma unroll
            for (int ks = 0; ks < 2; ks++)
                #pragma unroll
                for (int mi = 0; mi < 2; mi++)
                    ldsm4(ah[ks][mi], Ab + ao + mi*1280 + ks*32);
            #pragma unroll
            for (int ks = 0; ks < 2; ks++){
                #pragma unroll
                for (int nj = 0; nj < NI/2; nj++){
                    uint32_t bh[4];
                    ldsm4(bh, Bb + boff + nj*1280 + ks*32);
                    #pragma unroll
                    for (int mi = 0; mi < 2; mi++){
                        mma16816(acc[mi][2*nj],   ah[ks][mi], bh[0], bh[2]);
                        mma16816(acc[mi][2*nj+1], ah[ks][mi], bh[1], bh[3]);
                    }
                }
            }
        }
    }
#undef ISSUE_LOAD

    // epilogue: +bias -> fp16 NHWC (pre-GN), fused fp32 GN partial stats
    float s0=0.f, q0=0.f, s1=0.f, q1=0.f;
    __half* base = out + ((size_t)(b*K_H + h)*K_W)*Cout;
    #pragma unroll
    for (int mi = 0; mi < 2; mi++){
        int px = wm*32 + mi*16 + (lane >> 2);
        #pragma unroll
        for (int ni = 0; ni < NI; ni++){
            int co = cob + wn*(BN/2) + ni*8 + (lane & 3)*2;
            float bv0 = __ldg(bias + co), bv1 = __ldg(bias + co + 1);
            float v0 = acc[mi][ni][0] + bv0, v1 = acc[mi][ni][1] + bv1;
            float v2 = acc[mi][ni][2] + bv0, v3 = acc[mi][ni][3] + bv1;
            *(__half2*)(base + (size_t)px*Cout + co)     = __floats2half2_rn(v0, v1);
            *(__half2*)(base + (size_t)(px+8)*Cout + co) = __floats2half2_rn(v2, v3);
            if (ni < NI/2){ s0 += (v0+v1)+(v2+v3); q0 += v0*v0+v1*v1+v2*v2+v3*v3; }
            else          { s1 += (v0+v1)+(v2+v3); q1 += v0*v0+v1*v1+v2*v2+v3*v3; }
        }
    }
    #pragma unroll
    for (int o = 16; o; o >>= 1){
        s0 += __shfl_down_sync(0xffffffffu, s0, o);
        q0 += __shfl_down_sync(0xffffffffu, q0, o);
        s1 += __shfl_down_sync(0xffffffffu, s1, o);
        q1 += __shfl_down_sync(0xffffffffu, q1, o);
    }
    if (lane == 0){
        constexpr int G = Cout/Cg;
        int ch0 = cob + wn*(BN/2);
        int gbase = ch0/Cg;
        if ((BN/4) == Cg){
            atomicAdd(&g_gs[LAYER-1][b*G + gbase],     s0);
            atomicAdd(&g_gq[LAYER-1][b*G + gbase],     q0);
            atomicAdd(&g_gs[LAYER-1][b*G + gbase + 1], s1);
            atomicAdd(&g_gq[LAYER-1][b*G + gbase + 1], q1);
        } else {
            atomicAdd(&g_gs[LAYER-1][b*G + gbase], s0 + s1);
            atomicAdd(&g_gq[LAYER-1][b*G + gbase], q0 + q1);
        }
    }
}

// ======================= segment pooling (GN3 finalize + relu fused) =======================
__global__ void pool_seg(const int* __restrict__ masks, const float* __restrict__ gamma,
                         const float* __restrict__ beta){
    __shared__ float sacc[K_NS][64];
    __shared__ float scnt[K_NS];
    int bh = blockIdx.x;
    int b = bh >> 7;
    int tid = threadIdx.x;
    for (int i = tid; i < K_NS*64; i += 256) (&sacc[0][0])[i] = 0.f;
    if (tid < K_NS) scnt[tid] = 0.f;
    __syncthreads();

    int c = tid & 63, g = tid >> 6;
    int gi = b*4 + (c >> 4);
    const float n3 = 16.f * (float)K_HW;
    float mu  = g_gs[2][gi] / n3;
    float var = g_gq[2][gi] / n3 - mu*mu;
    float inv = rsqrtf(var + 1e-5f);
    float s = gamma[c]*inv;
    float t = beta[c] - mu*s;

    const __half* yb = g_y3 + (size_t)bh*K_W*64;
    const int* mrow = masks + (size_t)bh*K_W;
    for (int px = g; px < K_W; px += 4){
        int seg = mrow[px];
        float v = fmaxf(fmaf(s, __half2float(yb[(size_t)px*64 + c]), t), 0.f);
        atomicAdd(&sacc[seg][c], v);
        if (c == 0) atomicAdd(&scnt[seg], 1.f);
    }
    __syncthreads();
    for (int i = tid; i < K_NS*64; i += 256) atomicAdd(&g_psum[b*K_NS*64 + i], (&sacc[0][0])[i]);
    if (tid < K_NS) atomicAdd(&g_pcnt[b*K_NS + tid], scnt[tid]);
}

// ======================= heads =======================
__global__ void heads(const float* __restrict__ wbox, const float* __restrict__ bbox,
                      const float* __restrict__ wconf, const float* __restrict__ bconf,
                      float* __restrict__ outp){
    int t = threadIdx.x;
    if (t >= K_B*32) return;
    int b = t / 32, o = t % 32, s = o + 1;
    float inv = 1.f / fmaxf(g_pcnt[b*K_NS + s], 1e-4f);
    const float* ps = &g_psum[(b*K_NS + s)*64];
    float pooled[64];
    #pragma unroll
    for (int c = 0; c < 64; c++) pooled[c] = ps[c]*inv;
    #pragma unroll
    for (int k = 0; k < 7; k++){
        float d = bbox[k];
        #pragma unroll
        for (int c = 0; c < 64; c++) d = fmaf(pooled[c], wbox[k*64+c], d);
        outp[(b*32 + o)*7 + k] = d;
    }
    float d = bconf[0];
    #pragma unroll
    for (int c = 0; c < 64; c++) d = fmaf(pooled[c], wconf[c], d);
    outp[K_B*32*7 + b*32 + o] = d;
}

// ======================= launch =======================
extern "C" void kernel_launch(void* const* d_in, const int* in_sizes, int n_in,
                              void* d_out, int out_size){
    const float* x      = (const float*)d_in[0];
    const int*   masks  = (const int*)  d_in[1];
    const float* wcoord = (const float*)d_in[2];
    const float* bcoord = (const float*)d_in[3];
    const float* w1     = (const float*)d_in[4];
    const float* b1     = (const float*)d_in[5];
    const float* gm1    = (const float*)d_in[6];
    const float* bt1    = (const float*)d_in[7];
    const float* w2     = (const float*)d_in[8];
    const float* b2     = (const float*)d_in[9];
    const float* gm2    = (const float*)d_in[10];
    const float* bt2    = (const float*)d_in[11];
    const float* w3     = (const float*)d_in[12];
    const float* b3     = (const float*)d_in[13];
    const float* gm3    = (const float*)d_in[14];
    const float* bt3    = (const float*)d_in[15];
    const float* wbox   = (const float*)d_in[16];
    const float* bbox   = (const float*)d_in[17];
    const float* wconf  = (const float*)d_in[18];
    const float* bconf  = (const float*)d_in[19];
    float* outp = (float*)d_out;

    const int SM12 = 2*10496 + 6*128*80;   // 82432 (BN=128)
    const int SM3  = 2*10496 + 6*64*80;    // 51712 (BN=64)
    cudaFuncSetAttribute(conv_hmma<1>, cudaFuncAttributeMaxDynamicSharedMemorySize, SM12);
    cudaFuncSetAttribute(conv_hmma<2>, cudaFuncAttributeMaxDynamicSharedMemorySize, SM12);
    cudaFuncSetAttribute(conv_hmma<3>, cudaFuncAttributeMaxDynamicSharedMemorySize, SM3);

    repack_all<<<929,256>>>(w1, w2, w3);
    { dim3 g(9, K_H, K_B); xform1<<<g,256>>>(x, wcoord, bcoord); }
    { dim3 g(K_H, K_B, 2); conv_hmma<1><<<g,256,SM12>>>(b1); }
    act_xform<2><<<(int)(((size_t)K_B*K_HW*256)/2048),256>>>(gm1, bt1);

    { dim3 g(K_H, K_B, 1); conv_hmma<2><<<g,256,SM12>>>(b2); }
    act_xform<3><<<(int)(((size_t)K_B*K_HW*128)/2048),256>>>(gm2, bt2);

    { dim3 g(K_H, K_B, 1); conv_hmma<3><<<g,256,SM3>>>(b3); }

    pool_seg<<<K_B*K_H,256>>>(masks, gm3, bt3);
    heads<<<1,128>>>(wbox, bbox, wconf, bconf, outp);
}

// round 16
// speedup vs baseline: 1.0107x; 1.0107x over previous
#include <cuda_runtime.h>
#include <cuda_fp16.h>
#include <cstdint>

#define K_H  128
#define K_W  128
#define K_HW 16384
#define K_B  4
#define K_NS 33

// ======================= device scratch (static, no alloc) =======================
__device__ __align__(16) __half g_a1[(size_t)(K_B*K_HW + 2*K_W)*576];
__device__ __align__(16) __half g_a2[(size_t)(K_B*K_HW + 2*K_W)*256];
__device__ __align__(16) __half g_a3[(size_t)(K_B*K_HW + 2*K_W)*128];
__device__ __align__(16) __half g_y1[(size_t)K_B*K_HW*256];   // pre-GN conv outs, fp16
__device__ __align__(16) __half g_y2[(size_t)K_B*K_HW*128];
__device__ __align__(16) __half g_y3[(size_t)K_B*K_HW*64];
__device__ __align__(16) __half g_w1[9*256*576];
__device__ __align__(16) __half g_w2[9*128*256];
__device__ __align__(16) __half g_w3[9*64*128];
__device__ float g_gs[3][64], g_gq[3][64];
__device__ float g_psum[K_B*K_NS*64];
__device__ float g_pcnt[K_B*K_NS];

// ======================= helpers =======================
__device__ __forceinline__ uint32_t smem_u32(const void* p) {
    uint32_t a;
    asm("{ .reg .u64 t; cvta.to.shared.u64 t, %1; cvt.u32.u64 %0, t; }" : "=r"(a) : "l"(p));
    return a;
}
__device__ __forceinline__ void cp16(uint32_t dst, const void* src, uint32_t sz){
    asm volatile("cp.async.cg.shared.global [%0], [%1], 16, %2;" :: "r"(dst), "l"(src), "r"(sz));
}
#define CP_COMMIT() asm volatile("cp.async.commit_group;" ::: "memory")
#define CP_WAIT0()  asm volatile("cp.async.wait_group 0;"  ::: "memory")
__device__ __forceinline__ void ldsm4(uint32_t (&r)[4], uint32_t a){
    asm volatile("ldmatrix.sync.aligned.m8n8.x4.shared.b16 {%0,%1,%2,%3}, [%4];"
        : "=r"(r[0]), "=r"(r[1]), "=r"(r[2]), "=r"(r[3]) : "r"(a));
}
__device__ __forceinline__ void mma16816(float (&d)[4], const uint32_t (&a)[4],
                                         uint32_t b0, uint32_t b1){
    asm volatile(
        "mma.sync.aligned.m16n8k16.row.col.f32.f16.f16.f32 "
        "{%0,%1,%2,%3},{%4,%5,%6,%7},{%8,%9},{%0,%1,%2,%3};"
        : "+f"(d[0]), "+f"(d[1]), "+f"(d[2]), "+f"(d[3])
        : "r"(a[0]), "r"(a[1]), "r"(a[2]), "r"(a[3]), "r"(b0), "r"(b1));
}

// ======================= setup: repack weights + zero accumulators (one launch) =======================
template<int LAYER>
__device__ __forceinline__ void repack_body(const float* __restrict__ w, int bid, int nb){
    constexpr int Cin  = (LAYER==1)?576:(LAYER==2)?256:128;
    constexpr int Cout = (LAYER==1)?256:(LAYER==2)?128:64;
    __half* wp = (LAYER==1)?g_w1:(LAYER==2)?g_w2:g_w3;
    int n = Cout*Cin*9;
    for (int i = bid*256 + threadIdx.x; i < n; i += nb*256){
        int k  = i % 9;
        int t  = i / 9;
        int ci = t % Cin;
        int co = t / Cin;
        wp[((size_t)k*Cout + co)*Cin + ci] = __float2half_rn(w[i]);
    }
}

__global__ void repack_all(const float* __restrict__ w1, const float* __restrict__ w2,
                           const float* __restrict__ w3){
    int bid = blockIdx.x;
    if (bid < 512)      repack_body<1>(w1, bid, 512);
    else if (bid < 768) repack_body<2>(w2, bid - 512, 256);
    else if (bid < 896) repack_body<3>(w3, bid - 768, 128);
    else {
        int i = (bid - 896)*256 + threadIdx.x;
        if (i < K_B*K_NS*64) g_psum[i] = 0.f;
        if (i < K_B*K_NS)    g_pcnt[i] = 0.f;
        if (i < 64){
            g_gs[0][i]=0.f; g_gs[1][i]=0.f; g_gs[2][i]=0.f;
            g_gq[0][i]=0.f; g_gq[1][i]=0.f; g_gq[2][i]=0.f;
        }
    }
}

__global__ void xform1(const float* __restrict__ x, const float* __restrict__ wc,
                       const float* __restrict__ bc){
    __shared__ float tile[64][129];
    int cblk = blockIdx.x, h = blockIdx.y, b = blockIdx.z, tid = threadIdx.x;
    if (cblk < 8){
        for (int i = tid; i < 64*128; i += 256){
            int ci = i >> 7, w = i & 127;
            tile[ci][w] = x[(((size_t)b*512 + cblk*64 + ci)*K_H + h)*K_W + w];
        }
    } else {
        for (int i = tid; i < 64*128; i += 256){
            int ci = i >> 7, w = i & 127;
            tile[ci][w] = fmaxf(wc[2*ci]*(float)w + wc[2*ci+1]*(float)h + bc[ci], 0.f);
        }
    }
    __syncthreads();
    for (int i = tid; i < 64*128; i += 256){
        int px = i >> 6, c = i & 63;
        size_t o = (size_t)(K_W)*576 + (((size_t)b*K_H + h)*K_W + px)*576 + cblk*64 + c;
        g_a1[o] = __float2half_rn(tile[c][px]);
    }
}

// GN finalize (inline) + relu + fp16 pack ; 8 elems/thread, fp16 in & out
template<int L>
__global__ void act_xform(const float* __restrict__ gamma, const float* __restrict__ beta){
    constexpr int C    = (L==2)?256:128;
    constexpr int Cg   = 32;
    constexpr int SIDX = L-2;
    const __half* __restrict__ y = (L==2)?g_y1:g_y2;
    __half* __restrict__ ah = ((L==2)?g_a2:g_a3) + (size_t)K_W*C;
    size_t i8 = ((size_t)blockIdx.x*256 + threadIdx.x)*8;
    if (i8 >= (size_t)K_B*K_HW*C) return;
    int c = (int)(i8 % C);
    int b = (int)(i8 / ((size_t)K_HW*C));
    int g = b*(C/Cg) + c/Cg;
    const float n   = (float)Cg * (float)K_HW;
    float mu  = g_gs[SIDX][g] / n;
    float var = g_gq[SIDX][g] / n - mu*mu;
    float inv = rsqrtf(var + 1e-5f);
    float4 gmA = *(const float4*)(gamma + c);
    float4 gmB = *(const float4*)(gamma + c + 4);
    float4 btA = *(const float4*)(beta  + c);
    float4 btB = *(const float4*)(beta  + c + 4);
    float s[8] = {gmA.x*inv, gmA.y*inv, gmA.z*inv, gmA.w*inv,
                  gmB.x*inv, gmB.y*inv, gmB.z*inv, gmB.w*inv};
    float t[8] = {btA.x - mu*s[0], btA.y - mu*s[1], btA.z - mu*s[2], btA.w - mu*s[3],
                  btB.x - mu*s[4], btB.y - mu*s[5], btB.z - mu*s[6], btB.w - mu*s[7]};
    uint4 raw = *(const uint4*)(y + i8);
    const __half2* hp = (const __half2*)&raw;
    __half2 o4[4];
    #pragma unroll
    for (int j = 0; j < 4; j++){
        float2 v = __half22float2(hp[j]);
        float r0 = fmaxf(fmaf(s[2*j],   v.x, t[2*j]),   0.f);
        float r1 = fmaxf(fmaf(s[2*j+1], v.y, t[2*j+1]), 0.f);
        o4[j] = __floats2half2_rn(r0, r1);
    }
    *(uint4*)(ah + i8) = *(uint4*)o4;
}

// ======================= conv3x3: plain fp16 mma.sync, BN=128, occ2, 1 barrier/group =======================
template<int LAYER>
__global__ void __launch_bounds__(256,2)
conv_hmma(const float* __restrict__ bias){
    constexpr int Cin  = (LAYER==1)?576:(LAYER==2)?256:128;
    constexpr int Cout = (LAYER==1)?256:(LAYER==2)?128:64;
    constexpr int Cg   = (LAYER==3)?16:32;
    constexpr int BN   = (Cout>=128)?128:64;
    constexpr int NCB  = Cin/32;
    constexpr int NG   = 3*NCB;
    constexpr int NI   = BN/16;
    constexpr int BIT  = BN/64;
    constexpr int APL  = 10496;
    constexpr int BPL  = BN*80;
    constexpr int ABYT = 2*APL;
    constexpr int WK   = Cout*Cin;
    constexpr int A_KYADJ = K_W*Cin - (NCB-1)*32;
    constexpr int W_KYADJ = 3*Cout*Cin - (NCB-1)*32;

    const __half* __restrict__ act = ((LAYER==1)?g_a1:(LAYER==2)?g_a2:g_a3) + (size_t)K_W*Cin;
    const __half* __restrict__ w_p = (LAYER==1)?g_w1:(LAYER==2)?g_w2:g_w3;
    __half* __restrict__ out = (LAYER==1)?g_y1:(LAYER==2)?g_y2:g_y3;

    extern __shared__ __align__(128) char dsm[];
    const uint32_t sbase = smem_u32(dsm);

    const int tid  = threadIdx.x;
    const int lane = tid & 31;
    const int wm   = (tid >> 5) & 3;
    const int wn   = tid >> 7;
    const int h    = blockIdx.x;
    const int b    = blockIdx.y;
    const int cob  = blockIdx.z*BN;

    if (tid < 80){
        int pl = tid/40, rem = tid%40;
        uint32_t row = (rem >= 20) ? 129u : 0u;
        *(uint32_t*)(dsm + pl*APL + row*80 + (rem%20)*4) = 0u;
    }

    float acc[2][NI][4];
    #pragma unroll
    for (int mi=0;mi<2;mi++)
        #pragma unroll
        for (int ni=0;ni<NI;ni++)
            #pragma unroll
            for (int j=0;j<4;j++) acc[mi][ni][j] = 0.f;

    uint32_t dA[2], dB[BIT];
    int atoff[2], wtoff[BIT];
    #pragma unroll
    for (int it = 0; it < 2; it++){
        int idx = it*256 + tid, r = idx >> 2, q = idx & 3;
        dA[it]    = sbase + (r+1)*80 + q*16;
        atoff[it] = r*Cin + q*8;
    }
    #pragma unroll
    for (int it = 0; it < BIT; it++){
        int idx = it*256 + tid, r = idx >> 2, q = idx & 3;
        dB[it]    = sbase + ABYT + r*80 + q*16;
        wtoff[it] = r*Cin + q*8;
    }

    const __half* pA = act + ((size_t)(b*K_H + h) - 1)*K_W*Cin;
    const __half* pW = w_p + (size_t)cob*Cin;
    int cbL = 0, kyL = 0;
    const uint32_t vmask = ((h > 0) ? 1u : 0u) | 2u | ((h < K_H-1) ? 4u : 0u);
    uint32_t szA = (vmask & 1u) ? 16u : 0u;

#define ISSUE_LOAD(POFF_A, POFF_B) { \
        _Pragma("unroll") \
        for (int it = 0; it < 2; it++) \
            cp16(dA[it] + (POFF_A), pA + atoff[it], szA); \
        _Pragma("unroll") \
        for (int kx = 0; kx < 3; kx++){ \
            _Pragma("unroll") \
            for (int it = 0; it < BIT; it++) \
                cp16(dB[it] + (POFF_B) + kx*BPL, pW + kx*WK + wtoff[it], 16u); \
        } \
        if (++cbL < NCB){ pA += 32; pW += 32; } \
        else { cbL = 0; ++kyL; pA += A_KYADJ; pW += W_KYADJ; \
               szA = ((vmask >> kyL) & 1u) ? 16u : 0u; } }

    const uint32_t aoff0 = (uint32_t)((wm*32 + (lane & 15))*80 + (lane >> 4)*16);
    const uint32_t boff  = (uint32_t)((wn*(BN/2) + (lane & 15))*80 + (lane >> 4)*16);

    uint32_t poffA = 0, poffB = 0;
    ISSUE_LOAD(0, 0); CP_COMMIT();

    #pragma unroll 1
    for (int g = 0; g < NG; ++g){
        CP_WAIT0();
        __syncthreads();

        if (g + 1 < NG) ISSUE_LOAD(APL - poffA, 3*BPL - poffB);
        CP_COMMIT();

        const uint32_t Ab  = sbase + poffA;
        const uint32_t Bb0 = sbase + ABYT + poffB;
        poffA ^= APL; poffB ^= 3*BPL;

        #pragma unroll
        for (int kx = 0; kx < 3; kx++){
            const uint32_t Bb = Bb0 + kx*BPL;
            const uint32_t ao = aoff0 + kx*80;
            uint32_t ah[2][2][4];
            #pragma unroll
            for (int ks = 0; ks < 2; ks++)
                #pragma unroll
                for (int mi = 0; mi < 2; mi++)
                    ldsm4(ah[ks][mi], Ab + ao + mi*1280 + ks*32);
            #pragma unroll
            for (int ks = 0; ks < 2; ks++){
                #pragma unroll
                for (int nj = 0; nj < NI/2; nj++){
                    uint32_t bh[4];
                    ldsm4(bh, Bb + boff + nj*1280 + ks*32);
                    #pragma unroll
                    for (int mi = 0; mi < 2; mi++){
                        mma16816(acc[mi][2*nj],   ah[ks][mi], bh[0], bh[2]);
                        mma16816(acc[mi][2*nj+1], ah[ks][mi], bh[1], bh[3]);
                    }
                }
            }
        }
    }
#undef ISSUE_LOAD

    // epilogue: +bias -> fp16 NHWC (pre-GN), fused fp32 GN partial stats
    float s0=0.f, q0=0.f, s1=0.f, q1=0.f;
    __half* base = out + ((size_t)(b*K_H + h)*K_W)*Cout;
    #pragma unroll
    for (int mi = 0; mi < 2; mi++){
        int px = wm*32 + mi*16 + (lane >> 2);
        #pragma unroll
        for (int ni = 0; ni < NI; ni++){
            int co = cob + wn*(BN/2) + ni*8 + (lane & 3)*2;
            float bv0 = __ldg(bias + co), bv1 = __ldg(bias + co + 1);
            float v0 = acc[mi][ni][0] + bv0, v1 = acc[mi][ni][1] + bv1;
            float v2 = acc[mi][ni][2] + bv0, v3 = acc[mi][ni][3] + bv1;
            *(__half2*)(base + (size_t)px*Cout + co)     = __floats2half2_rn(v0, v1);
            *(__half2*)(base + (size_t)(px+8)*Cout + co) = __floats2half2_rn(v2, v3);
            if (ni < NI/2){ s0 += (v0+v1)+(v2+v3); q0 += v0*v0+v1*v1+v2*v2+v3*v3; }
            else          { s1 += (v0+v1)+(v2+v3); q1 += v0*v0+v1*v1+v2*v2+v3*v3; }
        }
    }
    #pragma unroll
    for (int o = 16; o; o >>= 1){
        s0 += __shfl_down_sync(0xffffffffu, s0, o);
        q0 += __shfl_down_sync(0xffffffffu, q0, o);
        s1 += __shfl_down_sync(0xffffffffu, s1, o);
        q1 += __shfl_down_sync(0xffffffffu, q1, o);
    }
    if (lane == 0){
        constexpr int G = Cout/Cg;
        int ch0 = cob + wn*(BN/2);
        int gbase = ch0/Cg;
        if ((BN/4) == Cg){
            atomicAdd(&g_gs[LAYER-1][b*G + gbase],     s0);
            atomicAdd(&g_gq[LAYER-1][b*G + gbase],     q0);
            atomicAdd(&g_gs[LAYER-1][b*G + gbase + 1], s1);
            atomicAdd(&g_gq[LAYER-1][b*G + gbase + 1], q1);
        } else {
            atomicAdd(&g_gs[LAYER-1][b*G + gbase], s0 + s1);
            atomicAdd(&g_gq[LAYER-1][b*G + gbase], q0 + q1);
        }
    }
}

// ======================= segment pooling (GN3 finalize + relu fused), 512 threads =======================
__global__ void pool_seg(const int* __restrict__ masks, const float* __restrict__ gamma,
                         const float* __restrict__ beta){
    __shared__ float sacc[K_NS][64];
    __shared__ float scnt[K_NS];
    int bh = blockIdx.x;
    int b = bh >> 7;
    int tid = threadIdx.x;
    for (int i = tid; i < K_NS*64; i += 512) (&sacc[0][0])[i] = 0.f;
    if (tid < K_NS) scnt[tid] = 0.f;
    __syncthreads();

    int c = tid & 63, g = tid >> 6;          // 8 pixel groups of 16
    int gi = b*4 + (c >> 4);
    const float n3 = 16.f * (float)K_HW;
    float mu  = g_gs[2][gi] / n3;
    float var = g_gq[2][gi] / n3 - mu*mu;
    float inv = rsqrtf(var + 1e-5f);
    float s = __ldg(gamma + c)*inv;
    float t = __ldg(beta + c) - mu*s;

    const __half* yb = g_y3 + (size_t)bh*K_W*64;
    const int* mrow = masks + (size_t)bh*K_W;
    for (int px = g; px < K_W; px += 8){
        int seg = mrow[px];
        float v = fmaxf(fmaf(s, __half2float(yb[(size_t)px*64 + c]), t), 0.f);
        atomicAdd(&sacc[seg][c], v);
        if (c == 0) atomicAdd(&scnt[seg], 1.f);
    }
    __syncthreads();
    for (int i = tid; i < K_NS*64; i += 512) atomicAdd(&g_psum[b*K_NS*64 + i], (&sacc[0][0])[i]);
    if (tid < K_NS) atomicAdd(&g_pcnt[b*K_NS + tid], scnt[tid]);
}

// ======================= heads =======================
__global__ void heads(const float* __restrict__ wbox, const float* __restrict__ bbox,
                      const float* __restrict__ wconf, const float* __restrict__ bconf,
                      float* __restrict__ outp){
    int t = threadIdx.x;
    if (t >= K_B*32) return;
    int b = t / 32, o = t % 32, s = o + 1;
    float inv = 1.f / fmaxf(g_pcnt[b*K_NS + s], 1e-4f);
    const float* ps = &g_psum[(b*K_NS + s)*64];
    float pooled[64];
    #pragma unroll
    for (int c = 0; c < 64; c++) pooled[c] = ps[c]*inv;
    #pragma unroll
    for (int k = 0; k < 7; k++){
        float d = __ldg(bbox + k);
        #pragma unroll
        for (int c = 0; c < 64; c++) d = fmaf(pooled[c], __ldg(wbox + k*64 + c), d);
        outp[(b*32 + o)*7 + k] = d;
    }
    float d = __ldg(bconf);
    #pragma unroll
    for (int c = 0; c < 64; c++) d = fmaf(pooled[c], __ldg(wconf + c), d);
    outp[K_B*32*7 + b*32 + o] = d;
}

// ======================= launch =======================
extern "C" void kernel_launch(void* const* d_in, const int* in_sizes, int n_in,
                              void* d_out, int out_size){
    const float* x      = (const float*)d_in[0];
    const int*   masks  = (const int*)  d_in[1];
    const float* wcoord = (const float*)d_in[2];
    const float* bcoord = (const float*)d_in[3];
    const float* w1     = (const float*)d_in[4];
    const float* b1     = (const float*)d_in[5];
    const float* gm1    = (const float*)d_in[6];
    const float* bt1    = (const float*)d_in[7];
    const float* w2     = (const float*)d_in[8];
    const float* b2     = (const float*)d_in[9];
    const float* gm2    = (const float*)d_in[10];
    const float* bt2    = (const float*)d_in[11];
    const float* w3     = (const float*)d_in[12];
    const float* b3     = (const float*)d_in[13];
    const float* gm3    = (const float*)d_in[14];
    const float* bt3    = (const float*)d_in[15];
    const float* wbox   = (const float*)d_in[16];
    const float* bbox   = (const float*)d_in[17];
    const float* wconf  = (const float*)d_in[18];
    const float* bconf  = (const float*)d_in[19];
    float* outp = (float*)d_out;

    const int SM12 = 2*10496 + 6*128*80;   // 82432 (BN=128)
    const int SM3  = 2*10496 + 6*64*80;    // 51712 (BN=64)
    cudaFuncSetAttribute(conv_hmma<1>, cudaFuncAttributeMaxDynamicSharedMemorySize, SM12);
    cudaFuncSetAttribute(conv_hmma<2>, cudaFuncAttributeMaxDynamicSharedMemorySize, SM12);
    cudaFuncSetAttribute(conv_hmma<3>, cudaFuncAttributeMaxDynamicSharedMemorySize, SM3);

    repack_all<<<929,256>>>(w1, w2, w3);
    { dim3 g(9, K_H, K_B); xform1<<<g,256>>>(x, wcoord, bcoord); }
    { dim3 g(K_H, K_B, 2); conv_hmma<1><<<g,256,SM12>>>(b1); }
    act_xform<2><<<(int)(((size_t)K_B*K_HW*256)/2048),256>>>(gm1, bt1);

    { dim3 g(K_H, K_B, 1); conv_hmma<2><<<g,256,SM12>>>(b2); }
    act_xform<3><<<(int)(((size_t)K_B*K_HW*128)/2048),256>>>(gm2, bt2);

    { dim3 g(K_H, K_B, 1); conv_hmma<3><<<g,256,SM3>>>(b3); }

    pool_seg<<<K_B*K_H,512>>>(masks, gm3, bt3);
    heads<<<1,128>>>(wbox, bbox, wconf, bconf, outp);
}

// round 17
// speedup vs baseline: 1.0126x; 1.0018x over previous
#include <cuda_runtime.h>
#include <cuda_fp16.h>
#include <cstdint>

#define K_H  128
#define K_W  128
#define K_HW 16384
#define K_B  4
#define K_NS 33

// ======================= device scratch (static, no alloc) =======================
__device__ __align__(16) __half g_a1[(size_t)(K_B*K_HW + 2*K_W)*576];
__device__ __align__(16) __half g_a2[(size_t)(K_B*K_HW + 2*K_W)*256];
__device__ __align__(16) __half g_a3[(size_t)(K_B*K_HW + 2*K_W)*128];
__device__ __align__(16) __half g_y1[(size_t)K_B*K_HW*256];   // pre-GN conv outs, fp16
__device__ __align__(16) __half g_y2[(size_t)K_B*K_HW*128];
__device__ __align__(16) __half g_y3[(size_t)K_B*K_HW*64];
__device__ __align__(16) __half g_w1[9*256*576];
__device__ __align__(16) __half g_w2[9*128*256];
__device__ __align__(16) __half g_w3[9*64*128];
__device__ float g_gs[3][64], g_gq[3][64];
__device__ float g_psum[K_B*K_NS*64];
__device__ float g_pcnt[K_B*K_NS];

// ======================= helpers =======================
__device__ __forceinline__ uint32_t smem_u32(const void* p) {
    uint32_t a;
    asm("{ .reg .u64 t; cvta.to.shared.u64 t, %1; cvt.u32.u64 %0, t; }" : "=r"(a) : "l"(p));
    return a;
}
__device__ __forceinline__ void cp16(uint32_t dst, const void* src, uint32_t sz){
    asm volatile("cp.async.cg.shared.global [%0], [%1], 16, %2;" :: "r"(dst), "l"(src), "r"(sz));
}
#define CP_COMMIT() asm volatile("cp.async.commit_group;" ::: "memory")
#define CP_WAIT0()  asm volatile("cp.async.wait_group 0;"  ::: "memory")
__device__ __forceinline__ void ldsm4(uint32_t (&r)[4], uint32_t a){
    asm volatile("ldmatrix.sync.aligned.m8n8.x4.shared.b16 {%0,%1,%2,%3}, [%4];"
        : "=r"(r[0]), "=r"(r[1]), "=r"(r[2]), "=r"(r[3]) : "r"(a));
}
__device__ __forceinline__ void mma16816(float (&d)[4], const uint32_t (&a)[4],
                                         uint32_t b0, uint32_t b1){
    asm volatile(
        "mma.sync.aligned.m16n8k16.row.col.f32.f16.f16.f32 "
        "{%0,%1,%2,%3},{%4,%5,%6,%7},{%8,%9},{%0,%1,%2,%3};"
        : "+f"(d[0]), "+f"(d[1]), "+f"(d[2]), "+f"(d[3])
        : "r"(a[0]), "r"(a[1]), "r"(a[2]), "r"(a[3]), "r"(b0), "r"(b1));
}

// ======================= fused setup: repack + zero + xform1 (one launch) =======================
template<int LAYER>
__device__ __forceinline__ void repack_body(const float* __restrict__ w, int bid, int nb){
    constexpr int Cin  = (LAYER==1)?576:(LAYER==2)?256:128;
    constexpr int Cout = (LAYER==1)?256:(LAYER==2)?128:64;
    __half* wp = (LAYER==1)?g_w1:(LAYER==2)?g_w2:g_w3;
    int n = Cout*Cin*9;
    for (int i = bid*256 + threadIdx.x; i < n; i += nb*256){
        int k  = i % 9;
        int t  = i / 9;
        int ci = t % Cin;
        int co = t / Cin;
        wp[((size_t)k*Cout + co)*Cin + ci] = __float2half_rn(w[i]);
    }
}

__device__ __forceinline__ void xform1_body(const float* __restrict__ x,
                                            const float* __restrict__ wc,
                                            const float* __restrict__ bc, int bid){
    __shared__ float tile[64][129];
    int cblk = bid % 9;
    int t2   = bid / 9;
    int h    = t2 % K_H;
    int b    = t2 / K_H;
    int tid  = threadIdx.x;
    if (cblk < 8){
        for (int i = tid; i < 64*128; i += 256){
            int ci = i >> 7, w = i & 127;
            tile[ci][w] = x[(((size_t)b*512 + cblk*64 + ci)*K_H + h)*K_W + w];
        }
    } else {
        for (int i = tid; i < 64*128; i += 256){
            int ci = i >> 7, w = i & 127;
            tile[ci][w] = fmaxf(wc[2*ci]*(float)w + wc[2*ci+1]*(float)h + bc[ci], 0.f);
        }
    }
    __syncthreads();
    for (int i = tid; i < 64*128; i += 256){
        int px = i >> 6, c = i & 63;
        size_t o = (size_t)(K_W)*576 + (((size_t)b*K_H + h)*K_W + px)*576 + cblk*64 + c;
        g_a1[o] = __float2half_rn(tile[c][px]);
    }
}

// blocks: [0,4608) xform1 ; [4608,5120) repack1 ; [5120,5376) repack2 ;
//         [5376,5504) repack3 ; [5504,5537) zero
__global__ void setup_all(const float* __restrict__ x, const float* __restrict__ wc,
                          const float* __restrict__ bc,
                          const float* __restrict__ w1, const float* __restrict__ w2,
                          const float* __restrict__ w3){
    int bid = blockIdx.x;
    if (bid < 4608)      { xform1_body(x, wc, bc, bid); }
    else if (bid < 5120) repack_body<1>(w1, bid - 4608, 512);
    else if (bid < 5376) repack_body<2>(w2, bid - 5120, 256);
    else if (bid < 5504) repack_body<3>(w3, bid - 5376, 128);
    else {
        int i = (bid - 5504)*256 + threadIdx.x;
        if (i < K_B*K_NS*64) g_psum[i] = 0.f;
        if (i < K_B*K_NS)    g_pcnt[i] = 0.f;
        if (i < 64){
            g_gs[0][i]=0.f; g_gs[1][i]=0.f; g_gs[2][i]=0.f;
            g_gq[0][i]=0.f; g_gq[1][i]=0.f; g_gq[2][i]=0.f;
        }
    }
}

// GN finalize (inline) + relu + fp16 pack ; 8 elems/thread, fp16 in & out
template<int L>
__global__ void act_xform(const float* __restrict__ gamma, const float* __restrict__ beta){
    constexpr int C    = (L==2)?256:128;
    constexpr int Cg   = 32;
    constexpr int SIDX = L-2;
    const __half* __restrict__ y = (L==2)?g_y1:g_y2;
    __half* __restrict__ ah = ((L==2)?g_a2:g_a3) + (size_t)K_W*C;
    size_t i8 = ((size_t)blockIdx.x*256 + threadIdx.x)*8;
    if (i8 >= (size_t)K_B*K_HW*C) return;
    int c = (int)(i8 % C);
    int b = (int)(i8 / ((size_t)K_HW*C));
    int g = b*(C/Cg) + c/Cg;
    const float n   = (float)Cg * (float)K_HW;
    float mu  = g_gs[SIDX][g] / n;
    float var = g_gq[SIDX][g] / n - mu*mu;
    float inv = rsqrtf(var + 1e-5f);
    float4 gmA = *(const float4*)(gamma + c);
    float4 gmB = *(const float4*)(gamma + c + 4);
    float4 btA = *(const float4*)(beta  + c);
    float4 btB = *(const float4*)(beta  + c + 4);
    float s[8] = {gmA.x*inv, gmA.y*inv, gmA.z*inv, gmA.w*inv,
                  gmB.x*inv, gmB.y*inv, gmB.z*inv, gmB.w*inv};
    float t[8] = {btA.x - mu*s[0], btA.y - mu*s[1], btA.z - mu*s[2], btA.w - mu*s[3],
                  btB.x - mu*s[4], btB.y - mu*s[5], btB.z - mu*s[6], btB.w - mu*s[7]};
    uint4 raw = *(const uint4*)(y + i8);
    const __half2* hp = (const __half2*)&raw;
    __half2 o4[4];
    #pragma unroll
    for (int j = 0; j < 4; j++){
        float2 v = __half22float2(hp[j]);
        float r0 = fmaxf(fmaf(s[2*j],   v.x, t[2*j]),   0.f);
        float r1 = fmaxf(fmaf(s[2*j+1], v.y, t[2*j+1]), 0.f);
        o4[j] = __floats2half2_rn(r0, r1);
    }
    *(uint4*)(ah + i8) = *(uint4*)o4;
}

// ======================= conv3x3: plain fp16 mma.sync, BN=128, occ2, 1 barrier/group =======================
template<int LAYER>
__global__ void __launch_bounds__(256,2)
conv_hmma(const float* __restrict__ bias){
    constexpr int Cin  = (LAYER==1)?576:(LAYER==2)?256:128;
    constexpr int Cout = (LAYER==1)?256:(LAYER==2)?128:64;
    constexpr int Cg   = (LAYER==3)?16:32;
    constexpr int BN   = (Cout>=128)?128:64;
    constexpr int NCB  = Cin/32;
    constexpr int NG   = 3*NCB;
    constexpr int NI   = BN/16;
    constexpr int BIT  = BN/64;
    constexpr int APL  = 10496;
    constexpr int BPL  = BN*80;
    constexpr int ABYT = 2*APL;
    constexpr int WK   = Cout*Cin;
    constexpr int A_KYADJ = K_W*Cin - (NCB-1)*32;
    constexpr int W_KYADJ = 3*Cout*Cin - (NCB-1)*32;

    const __half* __restrict__ act = ((LAYER==1)?g_a1:(LAYER==2)?g_a2:g_a3) + (size_t)K_W*Cin;
    const __half* __restrict__ w_p = (LAYER==1)?g_w1:(LAYER==2)?g_w2:g_w3;
    __half* __restrict__ out = (LAYER==1)?g_y1:(LAYER==2)?g_y2:g_y3;

    extern __shared__ __align__(128) char dsm[];
    const uint32_t sbase = smem_u32(dsm);

    const int tid  = threadIdx.x;
    const int lane = tid & 31;
    const int wm   = (tid >> 5) & 3;
    const int wn   = tid >> 7;
    const int h    = blockIdx.x;
    const int b    = blockIdx.y;
    const int cob  = blockIdx.z*BN;

    if (tid < 80){
        int pl = tid/40, rem = tid%40;
        uint32_t row = (rem >= 20) ? 129u : 0u;
        *(uint32_t*)(dsm + pl*APL + row*80 + (rem%20)*4) = 0u;
    }

    float acc[2][NI][4];
    #pragma unroll
    for (int mi=0;mi<2;mi++)
        #pragma unroll
        for (int ni=0;ni<NI;ni++)
            #pragma unroll
            for (int j=0;j<4;j++) acc[mi][ni][j] = 0.f;

    uint32_t dA[2], dB[BIT];
    int atoff[2], wtoff[BIT];
    #pragma unroll
    for (int it = 0; it < 2; it++){
        int idx = it*256 + tid, r = idx >> 2, q = idx & 3;
        dA[it]    = sbase + (r+1)*80 + q*16;
        atoff[it] = r*Cin + q*8;
    }
    #pragma unroll
    for (int it = 0; it < BIT; it++){
        int idx = it*256 + tid, r = idx >> 2, q = idx & 3;
        dB[it]    = sbase + ABYT + r*80 + q*16;
        wtoff[it] = r*Cin + q*8;
    }

    const __half* pA = act + ((size_t)(b*K_H + h) - 1)*K_W*Cin;
    const __half* pW = w_p + (size_t)cob*Cin;
    int cbL = 0, kyL = 0;
    const uint32_t vmask = ((h > 0) ? 1u : 0u) | 2u | ((h < K_H-1) ? 4u : 0u);
    uint32_t szA = (vmask & 1u) ? 16u : 0u;

#define ISSUE_LOAD(POFF_A, POFF_B) { \
        _Pragma("unroll") \
        for (int it = 0; it < 2; it++) \
            cp16(dA[it] + (POFF_A), pA + atoff[it], szA); \
        _Pragma("unroll") \
        for (int kx = 0; kx < 3; kx++){ \
            _Pragma("unroll") \
            for (int it = 0; it < BIT; it++) \
                cp16(dB[it] + (POFF_B) + kx*BPL, pW + kx*WK + wtoff[it], 16u); \
        } \
        if (++cbL < NCB){ pA += 32; pW += 32; } \
        else { cbL = 0; ++kyL; pA += A_KYADJ; pW += W_KYADJ; \
               szA = ((vmask >> kyL) & 1u) ? 16u : 0u; } }

    const uint32_t aoff0 = (uint32_t)((wm*32 + (lane & 15))*80 + (lane >> 4)*16);
    const uint32_t boff  = (uint32_t)((wn*(BN/2) + (lane & 15))*80 + (lane >> 4)*16);

    uint32_t poffA = 0, poffB = 0;
    ISSUE_LOAD(0, 0); CP_COMMIT();

    #pragma unroll 1
    for (int g = 0; g < NG; ++g){
        CP_WAIT0();
        __syncthreads();

        if (g + 1 < NG) ISSUE_LOAD(APL - poffA, 3*BPL - poffB);
        CP_COMMIT();

        const uint32_t Ab  = sbase + poffA;
        const uint32_t Bb0 = sbase + ABYT + poffB;
        poffA ^= APL; poffB ^= 3*BPL;

        #pragma unroll
        for (int kx = 0; kx < 3; kx++){
            const uint32_t Bb = Bb0 + kx*BPL;
            const uint32_t ao = aoff0 + kx*80;
            uint32_t ah[2][2][4];
            #pragma unroll
            for (int ks = 0; ks < 2; ks++)
                #pragma unroll
                for (int mi = 0; mi < 2; mi++)
                    ldsm4(ah[ks][mi], Ab + ao + mi*1280 + ks*32);
            #pragma unroll
            for (int ks = 0; ks < 2; ks++){
                #pragma unroll
                for (int nj = 0; nj < NI/2; nj++){
                    uint32_t bh[4];
                    ldsm4(bh, Bb + boff + nj*1280 + ks*32);
                    #pragma unroll
                    for (int mi = 0; mi < 2; mi++){
                        mma16816(acc[mi][2*nj],   ah[ks][mi], bh[0], bh[2]);
                        mma16816(acc[mi][2*nj+1], ah[ks][mi], bh[1], bh[3]);
                    }
                }
            }
        }
    }
#undef ISSUE_LOAD

    // epilogue: +bias -> fp16 NHWC (pre-GN), fused fp32 GN partial stats
    float s0=0.f, q0=0.f, s1=0.f, q1=0.f;
    __half* base = out + ((size_t)(b*K_H + h)*K_W)*Cout;
    #pragma unroll
    for (int mi = 0; mi < 2; mi++){
        int px = wm*32 + mi*16 + (lane >> 2);
        #pragma unroll
        for (int ni = 0; ni < NI; ni++){
            int co = cob + wn*(BN/2) + ni*8 + (lane & 3)*2;
            float bv0 = __ldg(bias + co), bv1 = __ldg(bias + co + 1);
            float v0 = acc[mi][ni][0] + bv0, v1 = acc[mi][ni][1] + bv1;
            float v2 = acc[mi][ni][2] + bv0, v3 = acc[mi][ni][3] + bv1;
            *(__half2*)(base + (size_t)px*Cout + co)     = __floats2half2_rn(v0, v1);
            *(__half2*)(base + (size_t)(px+8)*Cout + co) = __floats2half2_rn(v2, v3);
            if (ni < NI/2){ s0 += (v0+v1)+(v2+v3); q0 += v0*v0+v1*v1+v2*v2+v3*v3; }
            else          { s1 += (v0+v1)+(v2+v3); q1 += v0*v0+v1*v1+v2*v2+v3*v3; }
        }
    }
    #pragma unroll
    for (int o = 16; o; o >>= 1){
        s0 += __shfl_down_sync(0xffffffffu, s0, o);
        q0 += __shfl_down_sync(0xffffffffu, q0, o);
        s1 += __shfl_down_sync(0xffffffffu, s1, o);
        q1 += __shfl_down_sync(0xffffffffu, q1, o);
    }
    if (lane == 0){
        constexpr int G = Cout/Cg;
        int ch0 = cob + wn*(BN/2);
        int gbase = ch0/Cg;
        if ((BN/4) == Cg){
            atomicAdd(&g_gs[LAYER-1][b*G + gbase],     s0);
            atomicAdd(&g_gq[LAYER-1][b*G + gbase],     q0);
            atomicAdd(&g_gs[LAYER-1][b*G + gbase + 1], s1);
            atomicAdd(&g_gq[LAYER-1][b*G + gbase + 1], q1);
        } else {
            atomicAdd(&g_gs[LAYER-1][b*G + gbase], s0 + s1);
            atomicAdd(&g_gq[LAYER-1][b*G + gbase], q0 + q1);
        }
    }
}

// ======================= segment pooling (GN3 finalize + relu fused), 512 threads =======================
__global__ void pool_seg(const int* __restrict__ masks, const float* __restrict__ gamma,
                         const float* __restrict__ beta){
    __shared__ float sacc[K_NS][64];
    __shared__ float scnt[K_NS];
    int bh = blockIdx.x;
    int b = bh >> 7;
    int tid = threadIdx.x;
    for (int i = tid; i < K_NS*64; i += 512) (&sacc[0][0])[i] = 0.f;
    if (tid < K_NS) scnt[tid] = 0.f;
    __syncthreads();

    int c = tid & 63, g = tid >> 6;
    int gi = b*4 + (c >> 4);
    const float n3 = 16.f * (float)K_HW;
    float mu  = g_gs[2][gi] / n3;
    float var = g_gq[2][gi] / n3 - mu*mu;
    float inv = rsqrtf(var + 1e-5f);
    float s = __ldg(gamma + c)*inv;
    float t = __ldg(beta + c) - mu*s;

    const __half* yb = g_y3 + (size_t)bh*K_W*64;
    const int* mrow = masks + (size_t)bh*K_W;
    for (int px = g; px < K_W; px += 8){
        int seg = mrow[px];
        float v = fmaxf(fmaf(s, __half2float(yb[(size_t)px*64 + c]), t), 0.f);
        atomicAdd(&sacc[seg][c], v);
        if (c == 0) atomicAdd(&scnt[seg], 1.f);
    }
    __syncthreads();
    for (int i = tid; i < K_NS*64; i += 512) atomicAdd(&g_psum[b*K_NS*64 + i], (&sacc[0][0])[i]);
    if (tid < K_NS) atomicAdd(&g_pcnt[b*K_NS + tid], scnt[tid]);
}

// ======================= heads =======================
__global__ void heads(const float* __restrict__ wbox, const float* __restrict__ bbox,
                      const float* __restrict__ wconf, const float* __restrict__ bconf,
                      float* __restrict__ outp){
    int t = threadIdx.x;
    if (t >= K_B*32) return;
    int b = t / 32, o = t % 32, s = o + 1;
    float inv = 1.f / fmaxf(g_pcnt[b*K_NS + s], 1e-4f);
    const float* ps = &g_psum[(b*K_NS + s)*64];
    float pooled[64];
    #pragma unroll
    for (int c = 0; c < 64; c++) pooled[c] = ps[c]*inv;
    #pragma unroll
    for (int k = 0; k < 7; k++){
        float d = __ldg(bbox + k);
        #pragma unroll
        for (int c = 0; c < 64; c++) d = fmaf(pooled[c], __ldg(wbox + k*64 + c), d);
        outp[(b*32 + o)*7 + k] = d;
    }
    float d = __ldg(bconf);
    #pragma unroll
    for (int c = 0; c < 64; c++) d = fmaf(pooled[c], __ldg(wconf + c), d);
    outp[K_B*32*7 + b*32 + o] = d;
}

// ======================= launch =======================
extern "C" void kernel_launch(void* const* d_in, const int* in_sizes, int n_in,
                              void* d_out, int out_size){
    const float* x      = (const float*)d_in[0];
    const int*   masks  = (const int*)  d_in[1];
    const float* wcoord = (const float*)d_in[2];
    const float* bcoord = (const float*)d_in[3];
    const float* w1     = (const float*)d_in[4];
    const float* b1     = (const float*)d_in[5];
    const float* gm1    = (const float*)d_in[6];
    const float* bt1    = (const float*)d_in[7];
    const float* w2     = (const float*)d_in[8];
    const float* b2     = (const float*)d_in[9];
    const float* gm2    = (const float*)d_in[10];
    const float* bt2    = (const float*)d_in[11];
    const float* w3     = (const float*)d_in[12];
    const float* b3     = (const float*)d_in[13];
    const float* gm3    = (const float*)d_in[14];
    const float* bt3    = (const float*)d_in[15];
    const float* wbox   = (const float*)d_in[16];
    const float* bbox   = (const float*)d_in[17];
    const float* wconf  = (const float*)d_in[18];
    const float* bconf  = (const float*)d_in[19];
    float* outp = (float*)d_out;

    const int SM12 = 2*10496 + 6*128*80;   // 82432 (BN=128)
    const int SM3  = 2*10496 + 6*64*80;    // 51712 (BN=64)
    cudaFuncSetAttribute(conv_hmma<1>, cudaFuncAttributeMaxDynamicSharedMemorySize, SM12);
    cudaFuncSetAttribute(conv_hmma<2>, cudaFuncAttributeMaxDynamicSharedMemorySize, SM12);
    cudaFuncSetAttribute(conv_hmma<3>, cudaFuncAttributeMaxDynamicSharedMemorySize, SM3);

    setup_all<<<5537,256>>>(x, wcoord, bcoord, w1, w2, w3);
    { dim3 g(K_H, K_B, 2); conv_hmma<1><<<g,256,SM12>>>(b1); }
    act_xform<2><<<(int)(((size_t)K_B*K_HW*256)/2048),256>>>(gm1, bt1);

    { dim3 g(K_H, K_B, 1); conv_hmma<2><<<g,256,SM12>>>(b2); }
    act_xform<3><<<(int)(((size_t)K_B*K_HW*128)/2048),256>>>(gm2, bt2);

    { dim3 g(K_H, K_B, 1); conv_hmma<3><<<g,256,SM3>>>(b3); }

    pool_seg<<<K_B*K_H,512>>>(masks, gm3, bt3);
    heads<<<1,128>>>(wbox, bbox, wconf, bconf, outp);
}